// round 1
// baseline (speedup 1.0000x reference)
#include <cuda_runtime.h>

#define FULLMASK 0xffffffffu

// Gather partner amplitudes across register-bit mask MR (compile-time) and
// lane-bit mask ml (runtime, warp-uniform).
template<int MR>
__device__ __forceinline__ void gatherT(const float* s, float* p, int ml) {
#pragma unroll
    for (int r = 0; r < 8; r++) {
        float v = s[r ^ MR];
        if (ml) v = __shfl_xor_sync(FULLMASK, v, ml);
        p[r] = v;
    }
}

__device__ __forceinline__ void exch(const float* s, float* p, int mr, int ml) {
    switch (mr & 7) {
        case 0: gatherT<0>(s, p, ml); break;
        case 1: gatherT<1>(s, p, ml); break;
        case 2: gatherT<2>(s, p, ml); break;
        case 3: gatherT<3>(s, p, ml); break;
        case 4: gatherT<4>(s, p, ml); break;
        case 5: gatherT<5>(s, p, ml); break;
        case 6: gatherT<6>(s, p, ml); break;
        default: gatherT<7>(s, p, ml); break;
    }
}

// General complex 2x2 gate on bit b.
__device__ __forceinline__ void apply1q(float re[8], float im[8], int lane, int b,
                                        float u00r, float u00i, float u01r, float u01i,
                                        float u10r, float u10i, float u11r, float u11i) {
    float pre[8], pim[8];
    int m = 1 << b;
    exch(re, pre, m >> 5, m & 31);
    exch(im, pim, m >> 5, m & 31);
#pragma unroll
    for (int r = 0; r < 8; r++) {
        int i = (r << 5) | lane;
        int bit = (i >> b) & 1;
        float csr = bit ? u11r : u00r, csi = bit ? u11i : u00i;
        float cpr = bit ? u10r : u01r, cpi = bit ? u10i : u01i;
        float ar = re[r], ai = im[r], pr = pre[r], pi = pim[r];
        re[r] = csr * ar - csi * ai + cpr * pr - cpi * pi;
        im[r] = csr * ai + csi * ar + cpr * pi + cpi * pr;
    }
}

// Real 2x2 gate on bit b (RY, H).
__device__ __forceinline__ void apply1q_real(float re[8], float im[8], int lane, int b,
                                             float u00, float u01, float u10, float u11) {
    float pre[8], pim[8];
    int m = 1 << b;
    exch(re, pre, m >> 5, m & 31);
    exch(im, pim, m >> 5, m & 31);
#pragma unroll
    for (int r = 0; r < 8; r++) {
        int i = (r << 5) | lane;
        int bit = (i >> b) & 1;
        float cs = bit ? u11 : u00;
        float cp = bit ? u10 : u01;
        re[r] = cs * re[r] + cp * pre[r];
        im[r] = cs * im[r] + cp * pim[r];
    }
}

// Conditional swap of a[i] <-> a[i^m] where (i & need1) == need1 and,
// if dA >= 0, bits dA and dB of i differ. Used for PX/CNOT/CSWAP/TOF.
__device__ __forceinline__ void perm_swap(float re[8], float im[8], int lane, int m,
                                          int need1, int dA, int dB) {
    float pre[8], pim[8];
    exch(re, pre, m >> 5, m & 31);
    exch(im, pim, m >> 5, m & 31);
#pragma unroll
    for (int r = 0; r < 8; r++) {
        int i = (r << 5) | lane;
        bool sw = ((i & need1) == need1);
        if (dA >= 0) sw = sw && ((((i >> dA) ^ (i >> dB)) & 1) != 0);
        re[r] = sw ? pre[r] : re[r];
        im[r] = sw ? pim[r] : im[r];
    }
}

// Negate amplitudes where all bits in need1 are set (PZ, CZ).
__device__ __forceinline__ void diag_negate(float re[8], float im[8], int lane, int need1) {
#pragma unroll
    for (int r = 0; r < 8; r++) {
        int i = (r << 5) | lane;
        if ((i & need1) == need1) { re[r] = -re[r]; im[r] = -im[r]; }
    }
}

// RZ(theta): diag(c - i s, c + i s), c=cos(t/2), s=sin(t/2)
__device__ __forceinline__ void apply_rz(float re[8], float im[8], int lane, int b,
                                         float c, float s) {
#pragma unroll
    for (int r = 0; r < 8; r++) {
        int i = (r << 5) | lane;
        float sg = ((i >> b) & 1) ? s : -s;
        float ar = re[r], ai = im[r];
        re[r] = c * ar - sg * ai;
        im[r] = c * ai + sg * ar;
    }
}

__global__ void __launch_bounds__(256) qsim_kernel(
    const float* __restrict__ feats,   // [B, 8]
    const float* __restrict__ qp,      // [48]
    const int* __restrict__ dry,       // [24]
    const int* __restrict__ drot,      // [24]
    const int* __restrict__ dg2,       // [24]
    float* __restrict__ out,           // [B, 8]
    int batch) {
    int w = (int)((blockIdx.x * blockDim.x + threadIdx.x) >> 5);
    int lane = threadIdx.x & 31;
    if (w >= batch) return;

    // lanes 0..7 hold feature angles; precompute cos/sin of theta/2
    float fv = feats[w * 8 + (lane & 7)];
    float fs_, fc_;
    __sincosf(0.5f * fv, &fs_, &fc_);

    // H^8 |0...0> : uniform amplitude 1/16
    float re[8], im[8];
#pragma unroll
    for (int r = 0; r < 8; r++) { re[r] = 0.0625f; im[r] = 0.0f; }

#pragma unroll 1
    for (int layer = 0; layer < 6; ++layer) {
#pragma unroll 1
        for (int node = 0; node < 8; ++node) {
            int di = layer * 4 + (node & 3);
            int b = 7 - node;  // wire w -> bit 7-w
            if (__ldg(&dry[di])) {
                float c = __shfl_sync(FULLMASK, fc_, node);
                float s = __shfl_sync(FULLMASK, fs_, node);
                apply1q_real(re, im, lane, b, c, -s, s, c);  // RY
            }
            int rot = __ldg(&drot[di]);
            if (rot < 3) {
                float th = __ldg(&qp[layer * 8 + node]);
                float s, c;
                __sincosf(0.5f * th, &s, &c);
                if (rot == 0)
                    apply1q(re, im, lane, b, c, 0.f, 0.f, -s, 0.f, -s, c, 0.f);  // RX
                else if (rot == 1)
                    apply1q_real(re, im, lane, b, c, -s, s, c);                  // RY
                else
                    apply_rz(re, im, lane, b, c, s);                             // RZ
            }
            int g2 = __ldg(&dg2[di]);
            if (g2) {
                int n1 = (node + 1) & 7, n2 = (node + 2) & 7;
                int b1 = 7 - n1, b2 = 7 - n2;
                const float rh = 0.70710678118654752f;
                switch (g2) {
                    case 1:  // H
                        apply1q_real(re, im, lane, b, rh, rh, rh, -rh);
                        break;
                    case 2:  // PauliX: unconditional swap across bit b
                        perm_swap(re, im, lane, 1 << b, 0, -1, 0);
                        break;
                    case 3:  // PauliY: [[0,-i],[i,0]]
                        apply1q(re, im, lane, b, 0.f, 0.f, 0.f, -1.f, 0.f, 1.f, 0.f, 0.f);
                        break;
                    case 4:  // PauliZ
                        diag_negate(re, im, lane, 1 << b);
                        break;
                    case 5:  // CNOT: control=node(bit b), target=n1(bit b1)
                        perm_swap(re, im, lane, 1 << b1, 1 << b, -1, 0);
                        break;
                    case 6:  // CSWAP: control=node, swap wires n1,n2
                        perm_swap(re, im, lane, (1 << b1) | (1 << b2), 1 << b, b1, b2);
                        break;
                    case 7:  // Toffoli: controls node,n1, target n2
                        perm_swap(re, im, lane, 1 << b2, (1 << b) | (1 << b1), -1, 0);
                        break;
                    case 8:  // CZ
                        diag_negate(re, im, lane, (1 << b) | (1 << b1));
                        break;
                    default:
                        break;
                }
            }
        }
    }

    // Measurement: <Z_p> = sum_i |a_i|^2 * (1 - 2*bit_{7-p}(i))
    float acc[8];
#pragma unroll
    for (int p = 0; p < 8; p++) acc[p] = 0.f;
#pragma unroll
    for (int r = 0; r < 8; r++) {
        float pr = re[r] * re[r] + im[r] * im[r];
        int i = (r << 5) | lane;
#pragma unroll
        for (int p = 0; p < 8; p++) {
            acc[p] += ((i >> (7 - p)) & 1) ? -pr : pr;
        }
    }
#pragma unroll
    for (int p = 0; p < 8; p++) {
#pragma unroll
        for (int off = 16; off; off >>= 1)
            acc[p] += __shfl_xor_sync(FULLMASK, acc[p], off);
    }
    if (lane == 0) {
        float4* o = reinterpret_cast<float4*>(out + (size_t)w * 8);
        o[0] = make_float4(acc[0], acc[1], acc[2], acc[3]);
        o[1] = make_float4(acc[4], acc[5], acc[6], acc[7]);
    }
}

extern "C" void kernel_launch(void* const* d_in, const int* in_sizes, int n_in,
                              void* d_out, int out_size) {
    const float* feats = (const float*)d_in[0];   // [B, 8] float32
    const float* qp    = (const float*)d_in[1];   // [48] float32
    const int* dry     = (const int*)d_in[2];     // [6,4] int32
    const int* drot    = (const int*)d_in[3];     // [6,4] int32
    const int* dg2     = (const int*)d_in[4];     // [6,4] int32
    float* out         = (float*)d_out;           // [B, 8] float32

    int batch = in_sizes[0] / 8;
    int threads = 256;
    int total_threads = batch * 32;
    int blocks = (total_threads + threads - 1) / threads;
    qsim_kernel<<<blocks, threads>>>(feats, qp, dry, drot, dg2, out, batch);
}

// round 3
// speedup vs baseline: 2.3211x; 2.3211x over previous
#include <cuda_runtime.h>

#define FULLMASK 0xffffffffu

// ---------------------------------------------------------------------------
// State layout: amplitude index i (8 bits) = (r << 5) | lane.
// wire w  <->  bit (7 - w).  Bits 0..4 = lane bits, bits 5..7 = register bits.
// Each lane holds re[8], im[8].
// All gate templates take compile-time bit positions -> no per-element index
// math, no dynamic register indexing, hoisted lane-dependent selects.
// ---------------------------------------------------------------------------

template<int B>
__device__ __forceinline__ float lshfl(float v) {
    return __shfl_xor_sync(FULLMASK, v, 1 << B);
}

// RY / any real gate [c,-s; s,c]
template<int B>
__device__ __forceinline__ void g_ry(float re[8], float im[8], int lane, float c, float s) {
    if constexpr (B >= 5) {
        constexpr int M = 1 << (B - 5);
#pragma unroll
        for (int r = 0; r < 8; r++) {
            if ((r & M) == 0) {
                int r1 = r | M;
                float a0 = re[r], a1 = re[r1];
                re[r]  = c * a0 - s * a1;
                re[r1] = s * a0 + c * a1;
                a0 = im[r]; a1 = im[r1];
                im[r]  = c * a0 - s * a1;
                im[r1] = s * a0 + c * a1;
            }
        }
    } else {
        float sp = ((lane >> B) & 1) ? s : -s;   // hoisted: 1 SEL per gate
#pragma unroll
        for (int r = 0; r < 8; r++) {
            float pr = lshfl<B>(re[r]);
            float pi = lshfl<B>(im[r]);
            re[r] = c * re[r] + sp * pr;
            im[r] = c * im[r] + sp * pi;
        }
    }
}

// RX: re' = c*re + s*p_im ; im' = c*im - s*p_re   (same formula both halves)
template<int B>
__device__ __forceinline__ void g_rx(float re[8], float im[8], float c, float s) {
    if constexpr (B >= 5) {
        constexpr int M = 1 << (B - 5);
#pragma unroll
        for (int r = 0; r < 8; r++) {
            if ((r & M) == 0) {
                int r1 = r | M;
                float r0 = re[r], i0 = im[r], r1v = re[r1], i1 = im[r1];
                re[r]  = c * r0  + s * i1;
                im[r]  = c * i0  - s * r1v;
                re[r1] = c * r1v + s * i0;
                im[r1] = c * i1  - s * r0;
            }
        }
    } else {
#pragma unroll
        for (int r = 0; r < 8; r++) {
            float pr = lshfl<B>(re[r]);
            float pi = lshfl<B>(im[r]);
            re[r] = c * re[r] + s * pi;
            im[r] = c * im[r] - s * pr;
        }
    }
}

// RZ: diagonal.  t = bit ? s : -s; re'=c*re - t*im; im'=c*im + t*re
template<int B>
__device__ __forceinline__ void g_rz(float re[8], float im[8], int lane, float c, float s) {
    if constexpr (B >= 5) {
        constexpr int M = 1 << (B - 5);
#pragma unroll
        for (int r = 0; r < 8; r++) {
            float t = (r & M) ? s : -s;          // compile-time sign
            float ar = re[r], ai = im[r];
            re[r] = c * ar - t * ai;
            im[r] = c * ai + t * ar;
        }
    } else {
        float t = ((lane >> B) & 1) ? s : -s;    // hoisted
#pragma unroll
        for (int r = 0; r < 8; r++) {
            float ar = re[r], ai = im[r];
            re[r] = c * ar - t * ai;
            im[r] = c * ai + t * ar;
        }
    }
}

// Hadamard
template<int B>
__device__ __forceinline__ void g_h(float re[8], float im[8], int lane) {
    const float rh = 0.70710678118654752440f;
    if constexpr (B >= 5) {
        constexpr int M = 1 << (B - 5);
#pragma unroll
        for (int r = 0; r < 8; r++) {
            if ((r & M) == 0) {
                int r1 = r | M;
                float a = re[r], b = re[r1];
                re[r] = rh * (a + b); re[r1] = rh * (a - b);
                a = im[r]; b = im[r1];
                im[r] = rh * (a + b); im[r1] = rh * (a - b);
            }
        }
    } else {
        float sa = ((lane >> B) & 1) ? -rh : rh;
#pragma unroll
        for (int r = 0; r < 8; r++) {
            float pr = lshfl<B>(re[r]);
            float pi = lshfl<B>(im[r]);
            re[r] = sa * re[r] + rh * pr;
            im[r] = sa * im[r] + rh * pi;
        }
    }
}

// PauliY: bit0: re'=p_im, im'=-p_re ; bit1: re'=-p_im, im'=p_re
template<int B>
__device__ __forceinline__ void g_py(float re[8], float im[8], int lane) {
    if constexpr (B >= 5) {
        constexpr int M = 1 << (B - 5);
#pragma unroll
        for (int r = 0; r < 8; r++) {
            if ((r & M) == 0) {
                int r1 = r | M;
                float r0 = re[r], i0 = im[r], r1v = re[r1], i1 = im[r1];
                re[r]  =  i1;   im[r]  = -r1v;
                re[r1] = -i0;   im[r1] =  r0;
            }
        }
    } else {
        float sg  = ((lane >> B) & 1) ? -1.f : 1.f;
        float nsg = -sg;
#pragma unroll
        for (int r = 0; r < 8; r++) {
            float pr = lshfl<B>(re[r]);
            float pi = lshfl<B>(im[r]);
            re[r] = sg  * pi;
            im[r] = nsg * pr;
        }
    }
}

// PauliZ
template<int B>
__device__ __forceinline__ void g_pz(float re[8], float im[8], int lane) {
    if constexpr (B >= 5) {
        constexpr int M = 1 << (B - 5);
#pragma unroll
        for (int r = 0; r < 8; r++) {
            if (r & M) { re[r] = -re[r]; im[r] = -im[r]; }
        }
    } else {
        float sg = ((lane >> B) & 1) ? -1.f : 1.f;
#pragma unroll
        for (int r = 0; r < 8; r++) { re[r] *= sg; im[r] *= sg; }
    }
}

// CZ on bits BA, BB: negate where both bits are 1.
template<int BA, int BB>
__device__ __forceinline__ void g_cz(float re[8], float im[8], int lane) {
    bool lp = true;
    if constexpr (BA < 5) lp = lp && (((lane >> BA) & 1) != 0);
    if constexpr (BB < 5) lp = lp && (((lane >> BB) & 1) != 0);
    float sg = lp ? -1.f : 1.f;
#pragma unroll
    for (int r = 0; r < 8; r++) {
        bool rp = true;                              // compile-time per r
        if (BA >= 5) rp = rp && (((r >> (BA - 5)) & 1) != 0);
        if (BB >= 5) rp = rp && (((r >> (BB - 5)) & 1) != 0);
        if (rp) { re[r] *= sg; im[r] *= sg; }
    }
}

// Controlled-X: flip bit T where all bits of CM are 1.  CM==0 -> plain PauliX.
// Pair-safe: lane-target branch reads shuffled same-r values; register-target
// branch processes each {r, r|MT} pair exactly once.
template<int T, int CM>
__device__ __forceinline__ void g_cx(float re[8], float im[8], int lane) {
    constexpr int CML = CM & 31;
    constexpr int CMR = (CM >> 5) & 7;
    bool lp = ((lane & CML) == CML);                 // hoisted (true if CML==0)
    if constexpr (T < 5) {
#pragma unroll
        for (int r = 0; r < 8; r++) {
            if ((r & CMR) == CMR) {                  // compile-time per r
                float pr = lshfl<T>(re[r]);
                float pi = lshfl<T>(im[r]);
                if constexpr (CML == 0) { re[r] = pr; im[r] = pi; }
                else {
                    re[r] = lp ? pr : re[r];
                    im[r] = lp ? pi : im[r];
                }
            }
        }
    } else {
        constexpr int MT = 1 << (T - 5);
#pragma unroll
        for (int r = 0; r < 8; r++) {
            if (((r & CMR) == CMR) && !(r & MT)) {   // compile-time per r
                int r1 = r | MT;
                if constexpr (CML == 0) {
                    float t = re[r]; re[r] = re[r1]; re[r1] = t;
                    t = im[r]; im[r] = im[r1]; im[r1] = t;
                } else {
                    float a0 = re[r], a1 = re[r1];
                    re[r] = lp ? a1 : a0;  re[r1] = lp ? a0 : a1;
                    a0 = im[r]; a1 = im[r1];
                    im[r] = lp ? a1 : a0;  im[r1] = lp ? a0 : a1;
                }
            }
        }
    }
}

// Statically-impossible r for CSWAP<A,Bb,C> (no swap can occur for this r).
template<int A, int Bb, int C>
__device__ __forceinline__ constexpr bool cswap_possible(int r) {
    bool possible = true;
    if (C >= 5 && !((r >> (C - 5)) & 1)) possible = false;
    if (A >= 5 && Bb >= 5 &&
        (((r >> (A - 5)) & 1) == ((r >> (Bb - 5)) & 1))) possible = false;
    return possible;
}

// CSWAP: control bit C; swap bits A,Bb where they differ.
// GATHER-THEN-UPDATE: all partner reads complete before any write (the R2 bug
// was reading re[r^MR] after an earlier iteration had overwritten it).
template<int A, int Bb, int C>
__device__ __forceinline__ void g_cswap(float re[8], float im[8], int lane) {
    constexpr int M  = (1 << A) | (1 << Bb);
    constexpr int ML = M & 31;
    constexpr int MR = (M >> 5) & 7;
    float pre[8], pim[8];
#pragma unroll
    for (int r = 0; r < 8; r++) {
        if (cswap_possible<A, Bb, C>(r)) {           // compile-time prune
            float vr = re[r ^ MR], vi = im[r ^ MR];
            if constexpr (ML != 0) {
                vr = __shfl_xor_sync(FULLMASK, vr, ML);
                vi = __shfl_xor_sync(FULLMASK, vi, ML);
            }
            pre[r] = vr; pim[r] = vi;
        }
    }
    bool lctl = true;
    if constexpr (C < 5) lctl = (((lane >> C) & 1) != 0);
#pragma unroll
    for (int r = 0; r < 8; r++) {
        if (cswap_possible<A, Bb, C>(r)) {
            int ba = (A  < 5) ? ((lane >> A)  & 1) : ((r >> (A  - 5)) & 1);
            int bb = (Bb < 5) ? ((lane >> Bb) & 1) : ((r >> (Bb - 5)) & 1);
            bool ctl = lctl;
            if (C >= 5) ctl = (((r >> (C - 5)) & 1) != 0);
            bool sw = ctl && (ba != bb);
            re[r] = sw ? pre[r] : re[r];
            im[r] = sw ? pim[r] : im[r];
        }
    }
}

// ---------------------------------------------------------------------------

template<int NODE>
__device__ __forceinline__ void do_node(
    float re[8], float im[8], int lane, int layer,
    const int* __restrict__ dry, const int* __restrict__ drot,
    const int* __restrict__ dg2, const float* __restrict__ qp,
    float fc_, float fs_) {
    constexpr int B  = 7 - NODE;
    constexpr int N1 = (NODE + 1) & 7;
    constexpr int N2 = (NODE + 2) & 7;
    constexpr int B1 = 7 - N1;
    constexpr int B2 = 7 - N2;
    const int di = layer * 4 + (NODE & 3);

    if (__ldg(&dry[di])) {
        float c = __shfl_sync(FULLMASK, fc_, NODE);
        float s = __shfl_sync(FULLMASK, fs_, NODE);
        g_ry<B>(re, im, lane, c, s);
    }
    int rot = __ldg(&drot[di]);
    if (rot < 3) {
        float th = __ldg(&qp[layer * 8 + NODE]);
        float s, c;
        __sincosf(0.5f * th, &s, &c);
        if (rot == 0)      g_rx<B>(re, im, c, s);
        else if (rot == 1) g_ry<B>(re, im, lane, c, s);
        else               g_rz<B>(re, im, lane, c, s);
    }
    int g2 = __ldg(&dg2[di]);
    if (g2) {
        switch (g2) {
            case 1: g_h<B>(re, im, lane); break;
            case 2: g_cx<B, 0>(re, im, lane); break;
            case 3: g_py<B>(re, im, lane); break;
            case 4: g_pz<B>(re, im, lane); break;
            case 5: g_cx<B1, (1 << B)>(re, im, lane); break;              // CNOT
            case 6: g_cswap<B1, B2, B>(re, im, lane); break;              // CSWAP
            case 7: g_cx<B2, (1 << B) | (1 << B1)>(re, im, lane); break;  // Toffoli
            case 8: g_cz<B, B1>(re, im, lane); break;                     // CZ
            default: break;
        }
    }
}

__global__ void __launch_bounds__(256) qsim_kernel(
    const float* __restrict__ feats,   // [B, 8]
    const float* __restrict__ qp,      // [48]
    const int* __restrict__ dry,       // [24]
    const int* __restrict__ drot,      // [24]
    const int* __restrict__ dg2,       // [24]
    float* __restrict__ out,           // [B, 8]
    int batch) {
    int w = (int)((blockIdx.x * blockDim.x + threadIdx.x) >> 5);
    int lane = threadIdx.x & 31;
    if (w >= batch) return;

    // lanes 0..7 hold feature angles; precompute cos/sin(theta/2)
    float fv = feats[w * 8 + (lane & 7)];
    float fs_, fc_;
    __sincosf(0.5f * fv, &fs_, &fc_);

    // H^8 |0...0>  ==  uniform 1/16 real amplitude
    float re[8], im[8];
#pragma unroll
    for (int r = 0; r < 8; r++) { re[r] = 0.0625f; im[r] = 0.0f; }

#pragma unroll 1
    for (int layer = 0; layer < 6; ++layer) {
        do_node<0>(re, im, lane, layer, dry, drot, dg2, qp, fc_, fs_);
        do_node<1>(re, im, lane, layer, dry, drot, dg2, qp, fc_, fs_);
        do_node<2>(re, im, lane, layer, dry, drot, dg2, qp, fc_, fs_);
        do_node<3>(re, im, lane, layer, dry, drot, dg2, qp, fc_, fs_);
        do_node<4>(re, im, lane, layer, dry, drot, dg2, qp, fc_, fs_);
        do_node<5>(re, im, lane, layer, dry, drot, dg2, qp, fc_, fs_);
        do_node<6>(re, im, lane, layer, dry, drot, dg2, qp, fc_, fs_);
        do_node<7>(re, im, lane, layer, dry, drot, dg2, qp, fc_, fs_);
    }

    // Measurement: <Z_p> = sum_i |a_i|^2 * (1 - 2*bit_{7-p}(i)),  i = (r<<5)|lane
    float acc[8];
#pragma unroll
    for (int p = 0; p < 8; p++) acc[p] = 0.f;
    float sgl[8];
#pragma unroll
    for (int p = 3; p < 8; p++)
        sgl[p] = ((lane >> (7 - p)) & 1) ? -1.f : 1.f;   // hoisted lane signs
#pragma unroll
    for (int r = 0; r < 8; r++) {
        float pr = re[r] * re[r] + im[r] * im[r];
        // register-bit wires (p=0,1,2 -> bits 7,6,5 -> reg bits 2,1,0): static signs
        acc[0] += ((r >> 2) & 1) ? -pr : pr;
        acc[1] += ((r >> 1) & 1) ? -pr : pr;
        acc[2] += (r & 1)        ? -pr : pr;
#pragma unroll
        for (int p = 3; p < 8; p++) acc[p] += sgl[p] * pr;
    }
#pragma unroll
    for (int p = 0; p < 8; p++) {
#pragma unroll
        for (int off = 16; off; off >>= 1)
            acc[p] += __shfl_xor_sync(FULLMASK, acc[p], off);
    }
    if (lane == 0) {
        float4* o = reinterpret_cast<float4*>(out + (size_t)w * 8);
        o[0] = make_float4(acc[0], acc[1], acc[2], acc[3]);
        o[1] = make_float4(acc[4], acc[5], acc[6], acc[7]);
    }
}

extern "C" void kernel_launch(void* const* d_in, const int* in_sizes, int n_in,
                              void* d_out, int out_size) {
    const float* feats = (const float*)d_in[0];   // [B, 8] float32
    const float* qp    = (const float*)d_in[1];   // [48]  float32
    const int* dry     = (const int*)d_in[2];     // [6,4] int32
    const int* drot    = (const int*)d_in[3];     // [6,4] int32
    const int* dg2     = (const int*)d_in[4];     // [6,4] int32
    float* out         = (float*)d_out;           // [B, 8] float32

    int batch = in_sizes[0] / 8;
    int threads = 256;
    int total_threads = batch * 32;
    int blocks = (total_threads + threads - 1) / threads;
    qsim_kernel<<<blocks, threads>>>(feats, qp, dry, drot, dg2, out, batch);
}

// round 4
// speedup vs baseline: 2.4966x; 1.0756x over previous
#include <cuda_runtime.h>

#define FULLMASK 0xffffffffu
typedef unsigned long long u64;

// ---------------------------------------------------------------------------
// State layout: amplitude index i (8 bits) = (r << 5) | lane.
// wire w <-> bit (7 - w). Bits 0..4 = lane bits, 5..7 = register bits.
// Each lane holds a[8]: packed complex amplitudes, lo32 = re, hi32 = im.
// Packed f32x2 math (FFMA2/FMUL2) halves fma-pipe instructions on gates whose
// coefficients are shared between re and im (RY, H) and folds sign flips.
// ---------------------------------------------------------------------------

__device__ __forceinline__ u64 pack2(float lo, float hi) {
    u64 r; asm("mov.b64 %0, {%1, %2};" : "=l"(r) : "f"(lo), "f"(hi)); return r;
}
__device__ __forceinline__ void unpack2(u64 v, float& lo, float& hi) {
    asm("mov.b64 {%0, %1}, %2;" : "=f"(lo), "=f"(hi) : "l"(v));
}
__device__ __forceinline__ u64 dup2(float x) { return pack2(x, x); }
__device__ __forceinline__ u64 fma2(u64 a, u64 b, u64 c) {
    u64 d; asm("fma.rn.f32x2 %0, %1, %2, %3;" : "=l"(d) : "l"(a), "l"(b), "l"(c)); return d;
}
__device__ __forceinline__ u64 mul2(u64 a, u64 b) {
    u64 d; asm("mul.rn.f32x2 %0, %1, %2;" : "=l"(d) : "l"(a), "l"(b)); return d;
}
__device__ __forceinline__ u64 swap2(u64 v) {  // (re,im) -> (im,re)
    float lo, hi; unpack2(v, lo, hi); return pack2(hi, lo);
}
template<int ML>
__device__ __forceinline__ u64 shfl2(u64 v) {
    float lo, hi; unpack2(v, lo, hi);
    lo = __shfl_xor_sync(FULLMASK, lo, ML);
    hi = __shfl_xor_sync(FULLMASK, hi, ML);
    return pack2(lo, hi);
}
template<int ML>
__device__ __forceinline__ u64 shfl2swap(u64 v) {  // partner, halves swapped (free)
    float lo, hi; unpack2(v, lo, hi);
    lo = __shfl_xor_sync(FULLMASK, lo, ML);
    hi = __shfl_xor_sync(FULLMASK, hi, ML);
    return pack2(hi, lo);
}

// ---------------------------- gates ----------------------------------------

// RY [c,-s; s,c] — same coeffs for re & im -> pure packed math.
template<int B>
__device__ __forceinline__ void g_ry(u64 a[8], int lane, float c, float s) {
    u64 cc = dup2(c);
    if constexpr (B >= 5) {
        constexpr int M = 1 << (B - 5);
        u64 ss = dup2(s), ns = dup2(-s);
#pragma unroll
        for (int r = 0; r < 8; r++) {
            if ((r & M) == 0) {
                int r1 = r | M;
                u64 v0 = a[r], v1 = a[r1];
                a[r]  = fma2(ns, v1, mul2(cc, v0));
                a[r1] = fma2(cc, v1, mul2(ss, v0));
            }
        }
    } else {
        u64 sp = dup2(((lane >> B) & 1) ? s : -s);   // hoisted
#pragma unroll
        for (int r = 0; r < 8; r++) {
            u64 p = shfl2<(1 << B)>(a[r]);
            a[r] = fma2(sp, p, mul2(cc, a[r]));
        }
    }
}

// RX: re' = c*re + s*p_im ; im' = c*im - s*p_re  -> coeff (s,-s) x swapped partner
template<int B>
__device__ __forceinline__ void g_rx(u64 a[8], float c, float s) {
    u64 cc = dup2(c), sn = pack2(s, -s);
    if constexpr (B >= 5) {
        constexpr int M = 1 << (B - 5);
#pragma unroll
        for (int r = 0; r < 8; r++) {
            if ((r & M) == 0) {
                int r1 = r | M;
                u64 v0 = a[r], v1 = a[r1];
                a[r]  = fma2(sn, swap2(v1), mul2(cc, v0));
                a[r1] = fma2(sn, swap2(v0), mul2(cc, v1));
            }
        }
    } else {
#pragma unroll
        for (int r = 0; r < 8; r++) {
            u64 p = shfl2swap<(1 << B)>(a[r]);       // (p_im, p_re), swap free
            a[r] = fma2(sn, p, mul2(cc, a[r]));
        }
    }
}

// RZ diagonal: re' = c*re - t*im ; im' = c*im + t*re, t = bit ? s : -s
template<int B>
__device__ __forceinline__ void g_rz(u64 a[8], int lane, float c, float s) {
    u64 cc = dup2(c);
    if constexpr (B >= 5) {
        constexpr int M = 1 << (B - 5);
        u64 k0 = pack2(s, -s);    // bit=0: t=-s -> (-t, t) = (s, -s)
        u64 k1 = pack2(-s, s);    // bit=1: t= s -> (-t, t) = (-s, s)
#pragma unroll
        for (int r = 0; r < 8; r++) {
            u64 k = (r & M) ? k1 : k0;               // compile-time pick
            a[r] = fma2(k, swap2(a[r]), mul2(cc, a[r]));
        }
    } else {
        float t = ((lane >> B) & 1) ? s : -s;        // hoisted
        u64 k = pack2(-t, t);
#pragma unroll
        for (int r = 0; r < 8; r++)
            a[r] = fma2(k, swap2(a[r]), mul2(cc, a[r]));
    }
}

// Hadamard
template<int B>
__device__ __forceinline__ void g_h(u64 a[8], int lane) {
    const float rh = 0.70710678118654752440f;
    u64 rh2 = dup2(rh);
    if constexpr (B >= 5) {
        constexpr int M = 1 << (B - 5);
        u64 nrh2 = dup2(-rh);
#pragma unroll
        for (int r = 0; r < 8; r++) {
            if ((r & M) == 0) {
                int r1 = r | M;
                u64 t = mul2(rh2, a[r]);
                u64 v1 = a[r1];
                a[r]  = fma2(rh2,  v1, t);
                a[r1] = fma2(nrh2, v1, t);
            }
        }
    } else {
        u64 sa = dup2(((lane >> B) & 1) ? -rh : rh);
#pragma unroll
        for (int r = 0; r < 8; r++) {
            u64 p = shfl2<(1 << B)>(a[r]);
            a[r] = fma2(rh2, p, mul2(sa, a[r]));
        }
    }
}

// PauliY: bit0: (re,im)' = ( p_im, -p_re) ; bit1: (-p_im, p_re)
template<int B>
__device__ __forceinline__ void g_py(u64 a[8], int lane) {
    if constexpr (B >= 5) {
        constexpr int M = 1 << (B - 5);
        u64 kp = pack2(1.f, -1.f), kn = pack2(-1.f, 1.f);
#pragma unroll
        for (int r = 0; r < 8; r++) {
            if ((r & M) == 0) {
                int r1 = r | M;
                u64 v0 = a[r], v1 = a[r1];
                a[r]  = mul2(kp, swap2(v1));
                a[r1] = mul2(kn, swap2(v0));
            }
        }
    } else {
        float sg = ((lane >> B) & 1) ? -1.f : 1.f;
        u64 k = pack2(sg, -sg);
#pragma unroll
        for (int r = 0; r < 8; r++) {
            u64 p = shfl2swap<(1 << B)>(a[r]);       // (p_im, p_re)
            a[r] = mul2(k, p);
        }
    }
}

// PauliZ
template<int B>
__device__ __forceinline__ void g_pz(u64 a[8], int lane) {
    if constexpr (B >= 5) {
        constexpr int M = 1 << (B - 5);
        u64 n1 = dup2(-1.f);
#pragma unroll
        for (int r = 0; r < 8; r++)
            if (r & M) a[r] = mul2(n1, a[r]);
    } else {
        u64 sg = dup2(((lane >> B) & 1) ? -1.f : 1.f);
#pragma unroll
        for (int r = 0; r < 8; r++) a[r] = mul2(sg, a[r]);
    }
}

// CZ on bits BA, BB
template<int BA, int BB>
__device__ __forceinline__ void g_cz(u64 a[8], int lane) {
    bool lp = true;
    if constexpr (BA < 5) lp = lp && (((lane >> BA) & 1) != 0);
    if constexpr (BB < 5) lp = lp && (((lane >> BB) & 1) != 0);
    u64 sg = dup2(lp ? -1.f : 1.f);
#pragma unroll
    for (int r = 0; r < 8; r++) {
        bool rp = true;                              // compile-time per r
        if (BA >= 5) rp = rp && (((r >> (BA - 5)) & 1) != 0);
        if (BB >= 5) rp = rp && (((r >> (BB - 5)) & 1) != 0);
        if (rp) a[r] = mul2(sg, a[r]);
    }
}

// Controlled-X: flip bit T where all CM bits set. CM==0 -> plain X.
template<int T, int CM>
__device__ __forceinline__ void g_cx(u64 a[8], int lane) {
    constexpr int CML = CM & 31;
    constexpr int CMR = (CM >> 5) & 7;
    bool lp = ((lane & CML) == CML);                 // true when CML==0
    if constexpr (T < 5) {
#pragma unroll
        for (int r = 0; r < 8; r++) {
            if ((r & CMR) == CMR) {                  // compile-time per r
                u64 p = shfl2<(1 << T)>(a[r]);
                if constexpr (CML == 0) a[r] = p;
                else a[r] = lp ? p : a[r];
            }
        }
    } else {
        constexpr int MT = 1 << (T - 5);
#pragma unroll
        for (int r = 0; r < 8; r++) {
            if (((r & CMR) == CMR) && !(r & MT)) {   // each pair once
                int r1 = r | MT;
                u64 v0 = a[r], v1 = a[r1];
                if constexpr (CML == 0) { a[r] = v1; a[r1] = v0; }
                else { a[r] = lp ? v1 : v0; a[r1] = lp ? v0 : v1; }
            }
        }
    }
}

template<int A, int Bb, int C>
__device__ __forceinline__ constexpr bool cswap_possible(int r) {
    bool possible = true;
    if (C >= 5 && !((r >> (C - 5)) & 1)) possible = false;
    if (A >= 5 && Bb >= 5 &&
        (((r >> (A - 5)) & 1) == ((r >> (Bb - 5)) & 1))) possible = false;
    return possible;
}

// CSWAP: control C; swap bits A,Bb where they differ. GATHER-THEN-UPDATE.
template<int A, int Bb, int C>
__device__ __forceinline__ void g_cswap(u64 a[8], int lane) {
    constexpr int M  = (1 << A) | (1 << Bb);
    constexpr int ML = M & 31;
    constexpr int MR = (M >> 5) & 7;
    u64 pa[8];
#pragma unroll
    for (int r = 0; r < 8; r++) {
        if (cswap_possible<A, Bb, C>(r)) {
            u64 v = a[r ^ MR];
            if constexpr (ML != 0) v = shfl2<ML>(v);
            pa[r] = v;
        }
    }
    bool lctl = true;
    if constexpr (C < 5) lctl = (((lane >> C) & 1) != 0);
#pragma unroll
    for (int r = 0; r < 8; r++) {
        if (cswap_possible<A, Bb, C>(r)) {
            int ba = (A  < 5) ? ((lane >> A)  & 1) : ((r >> (A  - 5)) & 1);
            int bb = (Bb < 5) ? ((lane >> Bb) & 1) : ((r >> (Bb - 5)) & 1);
            bool ctl = lctl;
            if (C >= 5) ctl = (((r >> (C - 5)) & 1) != 0);
            bool sw = ctl && (ba != bb);
            a[r] = sw ? pa[r] : a[r];
        }
    }
}

// ---------------------------------------------------------------------------
// Setup: fold design ints + sincos(qp/2) into one float4 per (layer, node).
// x = bits{0:dry, 1-2:rot, 3-6:g2} as int;  y = sin(th/2);  z = cos(th/2).
// ---------------------------------------------------------------------------
__device__ float4 g_gate[48];

__global__ void setup_kernel(const float* __restrict__ qp,
                             const int* __restrict__ dry,
                             const int* __restrict__ drot,
                             const int* __restrict__ dg2) {
    int i = threadIdx.x;
    if (i >= 48) return;
    int layer = i >> 3, node = i & 7;
    int di = layer * 4 + (node & 3);
    int code = (dry[di] & 1) | ((drot[di] & 3) << 1) | ((dg2[di] & 15) << 3);
    float s, c;
    __sincosf(0.5f * qp[i], &s, &c);
    g_gate[i] = make_float4(__int_as_float(code), s, c, 0.f);
}

// ---------------------------------------------------------------------------

template<int NODE>
__device__ __forceinline__ void do_node(u64 a[8], int lane, int layer,
                                        float fc_, float fs_) {
    constexpr int B  = 7 - NODE;
    constexpr int N1 = (NODE + 1) & 7;
    constexpr int N2 = (NODE + 2) & 7;
    constexpr int B1 = 7 - N1;
    constexpr int B2 = 7 - N2;

    float4 gi = g_gate[layer * 8 + NODE];
    int code = __float_as_int(gi.x);

    if (code & 1) {
        float c = __shfl_sync(FULLMASK, fc_, NODE);
        float s = __shfl_sync(FULLMASK, fs_, NODE);
        g_ry<B>(a, lane, c, s);
    }
    int rot = (code >> 1) & 3;
    if (rot < 3) {
        if (rot == 0)      g_rx<B>(a, gi.z, gi.y);
        else if (rot == 1) g_ry<B>(a, lane, gi.z, gi.y);
        else               g_rz<B>(a, lane, gi.z, gi.y);
    }
    int g2 = (code >> 3) & 15;
    if (g2) {
        switch (g2) {
            case 1: g_h<B>(a, lane); break;
            case 2: g_cx<B, 0>(a, lane); break;
            case 3: g_py<B>(a, lane); break;
            case 4: g_pz<B>(a, lane); break;
            case 5: g_cx<B1, (1 << B)>(a, lane); break;              // CNOT
            case 6: g_cswap<B1, B2, B>(a, lane); break;              // CSWAP
            case 7: g_cx<B2, (1 << B) | (1 << B1)>(a, lane); break;  // Toffoli
            case 8: g_cz<B, B1>(a, lane); break;                     // CZ
            default: break;
        }
    }
}

__global__ void __launch_bounds__(256) qsim_kernel(
    const float* __restrict__ feats,   // [B, 8]
    float* __restrict__ out,           // [B, 8]
    int batch) {
    int w = (int)((blockIdx.x * blockDim.x + threadIdx.x) >> 5);
    int lane = threadIdx.x & 31;
    if (w >= batch) return;

    float fv = feats[w * 8 + (lane & 7)];
    float fs_, fc_;
    __sincosf(0.5f * fv, &fs_, &fc_);

    // H^8 |0...0>  ==  uniform 1/16 real amplitude
    u64 a[8];
    u64 init = pack2(0.0625f, 0.0f);
#pragma unroll
    for (int r = 0; r < 8; r++) a[r] = init;

#pragma unroll 1
    for (int layer = 0; layer < 6; ++layer) {
        do_node<0>(a, lane, layer, fc_, fs_);
        do_node<1>(a, lane, layer, fc_, fs_);
        do_node<2>(a, lane, layer, fc_, fs_);
        do_node<3>(a, lane, layer, fc_, fs_);
        do_node<4>(a, lane, layer, fc_, fs_);
        do_node<5>(a, lane, layer, fc_, fs_);
        do_node<6>(a, lane, layer, fc_, fs_);
        do_node<7>(a, lane, layer, fc_, fs_);
    }

    // Measurement: <Z_p> = sum_i |a_i|^2 * (1 - 2*bit_{7-p}(i)),  i = (r<<5)|lane
    float acc[8];
#pragma unroll
    for (int p = 0; p < 8; p++) acc[p] = 0.f;
    float sgl[8];
#pragma unroll
    for (int p = 3; p < 8; p++)
        sgl[p] = ((lane >> (7 - p)) & 1) ? -1.f : 1.f;
#pragma unroll
    for (int r = 0; r < 8; r++) {
        float re, im;
        unpack2(a[r], re, im);
        float pr = fmaf(re, re, im * im);
        acc[0] += ((r >> 2) & 1) ? -pr : pr;
        acc[1] += ((r >> 1) & 1) ? -pr : pr;
        acc[2] += (r & 1)        ? -pr : pr;
#pragma unroll
        for (int p = 3; p < 8; p++) acc[p] += sgl[p] * pr;
    }
#pragma unroll
    for (int p = 0; p < 8; p++) {
#pragma unroll
        for (int off = 16; off; off >>= 1)
            acc[p] += __shfl_xor_sync(FULLMASK, acc[p], off);
    }
    if (lane == 0) {
        float4* o = reinterpret_cast<float4*>(out + (size_t)w * 8);
        o[0] = make_float4(acc[0], acc[1], acc[2], acc[3]);
        o[1] = make_float4(acc[4], acc[5], acc[6], acc[7]);
    }
}

extern "C" void kernel_launch(void* const* d_in, const int* in_sizes, int n_in,
                              void* d_out, int out_size) {
    const float* feats = (const float*)d_in[0];   // [B, 8] float32
    const float* qp    = (const float*)d_in[1];   // [48]  float32
    const int* dry     = (const int*)d_in[2];     // [6,4] int32
    const int* drot    = (const int*)d_in[3];     // [6,4] int32
    const int* dg2     = (const int*)d_in[4];     // [6,4] int32
    float* out         = (float*)d_out;           // [B, 8] float32

    int batch = in_sizes[0] / 8;
    setup_kernel<<<1, 64>>>(qp, dry, drot, dg2);
    int threads = 256;
    int total_threads = batch * 32;
    int blocks = (total_threads + threads - 1) / threads;
    qsim_kernel<<<blocks, threads>>>(feats, out, batch);
}